// round 2
// baseline (speedup 1.0000x reference)
#include <cuda_runtime.h>
#include <cuda_bf16.h>
#include <math_constants.h>

// ----------------------------------------------------------------------------
// MinArcSoftmaxLoss
//   theta = acos(costh); pos = theta[r, label]; mean/std(pos) (ddof=1)
//   d = mean + std*eps (0 at label col)
//   costh_mm = cos(theta - d);  costh_pm = cos(theta + M at label col only)
//   logits = S*(A*costh_mm + costh_pm)/(1+A); loss = -mean(log_softmax[label])
//
// Off-label algebra: cos(theta-d) = c*cos(d) + sqrt(1-c^2)*sin(d), pm = c.
// Fixed softmax shift of 64 (>= all logits) replaces the online max.
// Label dtype (int32 vs int64) is detected on-device: if int64, all odd
// int32 slots are zero high-words (values < 1e5); if int32 they are random
// labels, so a block-OR over odd slots disambiguates.
// ----------------------------------------------------------------------------

#define NSPLIT 4
#define MAXB   512

__device__ float g_mean;
__device__ float g_std;
__device__ int   g_is64;
__device__ float g_partial[MAXB * NSPLIT];

#define K1F   ((float)(64.0 * 0.1 / 1.1))                      // S*A/(1+A)
#define K2F   ((float)(64.0 / 1.1))                            // S/(1+A)
#define L1F   ((float)(64.0 * 0.1 / 1.1 * 1.4426950408889634)) // K1 * log2(e)
#define L2F   ((float)(64.0 / 1.1 * 1.4426950408889634))       // K2 * log2(e)
#define BIASF ((float)(64.0 * 1.4426950408889634))             // 64 * log2(e)
#define COSM  0.8775825618903728f                              // cos(0.5)
#define SINM  0.479425538604203f                               // sin(0.5)

__device__ __forceinline__ float fast_sin(float x) {
    float r; asm("sin.approx.ftz.f32 %0, %1;" : "=f"(r) : "f"(x)); return r;
}
__device__ __forceinline__ float fast_cos(float x) {
    float r; asm("cos.approx.ftz.f32 %0, %1;" : "=f"(r) : "f"(x)); return r;
}
__device__ __forceinline__ float fast_ex2(float x) {
    float r; asm("ex2.approx.ftz.f32 %0, %1;" : "=f"(r) : "f"(x)); return r;
}
__device__ __forceinline__ float fast_rsqrt(float x) {
    float r; asm("rsqrt.approx.ftz.f32 %0, %1;" : "=f"(r) : "f"(x)); return r;
}

__device__ __forceinline__ int get_label(const int* lab32, int r, int is64) {
    return is64 ? lab32[2 * r] : lab32[r];
}

// exp(logit - 64) using the off-label formula; used identically in the
// streaming kernel and the finalize fixup so the subtraction cancels exactly.
__device__ __forceinline__ float term(float c, float e, float mean, float stdv) {
    float d  = fmaf(e, stdv, mean);
    float sd = fast_sin(d);
    float cd = fast_cos(d);
    float s2 = fmaf(-c, c, 1.0f);           // 1 - c^2  (>= 0.0199)
    float s  = s2 * fast_rsqrt(s2);         // sqrt(1-c^2)
    float mm = fmaf(s, sd, c * cd);         // cos(theta - d)
    return fast_ex2(fmaf(L1F, mm, fmaf(L2F, c, -BIASF)));
}

// ---------------- kernel 1: dtype detect + mean/std of acos(pos) ------------
__global__ void stats_kernel(const float* __restrict__ costh,
                             const int* __restrict__ lab32,
                             int B, int C) {
    __shared__ float sh[MAXB];
    __shared__ float s_mean;
    __shared__ int   s_or;
    int r = threadIdx.x;

    if (r == 0) s_or = 0;
    __syncthreads();
    int odd = (r < B) ? lab32[2 * r + 1] : 0;   // high word if int64
    int w = __reduce_or_sync(0xffffffffu, odd);
    if ((threadIdx.x & 31) == 0 && w) atomicOr(&s_or, 1);
    __syncthreads();
    int is64 = (s_or == 0);
    if (r == 0) g_is64 = is64;

    float theta = 0.0f;
    if (r < B) {
        int lab = get_label(lab32, r, is64);
        float c = costh[(size_t)r * C + (size_t)lab];
        theta = acosf(c);
    }
    sh[r] = theta;
    __syncthreads();
    #pragma unroll
    for (int s = MAXB / 2; s > 0; s >>= 1) {
        if (r < s) sh[r] += sh[r + s];
        __syncthreads();
    }
    if (r == 0) s_mean = sh[0] / (float)B;
    __syncthreads();
    float mean = s_mean;
    float dev = (r < B) ? (theta - mean) : 0.0f;
    sh[r] = dev * dev;
    __syncthreads();
    #pragma unroll
    for (int s = MAXB / 2; s > 0; s >>= 1) {
        if (r < s) sh[r] += sh[r + s];
        __syncthreads();
    }
    if (r == 0) {
        g_mean = mean;
        g_std  = sqrtf(sh[0] / (float)(B - 1));   // ddof=1
    }
}

// ---------------- kernel 2: streaming exp-sum per (row, split) ---------------
__global__ void __launch_bounds__(256) main_kernel(const float* __restrict__ costh,
                                                   const float* __restrict__ eps,
                                                   int C) {
    int row   = blockIdx.x / NSPLIT;
    int split = blockIdx.x % NSPLIT;
    int chunk = C / NSPLIT;                 // 25000, % 4 == 0
    size_t base = (size_t)row * C + (size_t)split * chunk;
    const float4* __restrict__ c4 = (const float4*)(costh + base);
    const float4* __restrict__ e4 = (const float4*)(eps + base);
    int nvec = chunk >> 2;                  // 6250

    float mean = g_mean, stdv = g_std;
    float acc = 0.0f;
    for (int i = threadIdx.x; i < nvec; i += 256) {
        float4 c = c4[i];
        float4 e = e4[i];
        acc += term(c.x, e.x, mean, stdv);
        acc += term(c.y, e.y, mean, stdv);
        acc += term(c.z, e.z, mean, stdv);
        acc += term(c.w, e.w, mean, stdv);
    }

    __shared__ float sh[8];
    #pragma unroll
    for (int o = 16; o; o >>= 1) acc += __shfl_down_sync(0xffffffffu, acc, o);
    if ((threadIdx.x & 31) == 0) sh[threadIdx.x >> 5] = acc;
    __syncthreads();
    if (threadIdx.x < 32) {
        float v = (threadIdx.x < 8) ? sh[threadIdx.x] : 0.0f;
        #pragma unroll
        for (int o = 4; o; o >>= 1) v += __shfl_down_sync(0xffffffffu, v, o);
        if (threadIdx.x == 0) g_partial[row * NSPLIT + split] = v;
    }
}

// ---------------- kernel 3: label-column fixup + loss reduction --------------
__global__ void finalize_kernel(const float* __restrict__ costh,
                                const float* __restrict__ eps,
                                const int* __restrict__ lab32,
                                float* __restrict__ out,
                                int B, int C) {
    __shared__ float sh[MAXB];
    int r = threadIdx.x;
    float loss = 0.0f;
    if (r < B) {
        float sum = 0.0f;
        #pragma unroll
        for (int j = 0; j < NSPLIT; j++) sum += g_partial[r * NSPLIT + j];

        int lab = get_label(lab32, r, g_is64);
        size_t idx = (size_t)r * C + (size_t)lab;
        float cl = costh[idx];
        float el = eps[idx];

        // remove off-label-formula contribution at the label column
        float pw = term(cl, el, g_mean, g_std);

        // correct label logit: mm = cl (d=0); pm = cos(theta + M)
        float s2 = fmaf(-cl, cl, 1.0f);
        float sl = sqrtf(s2);
        float logit_r = fmaf(K1F, cl, K2F * fmaf(cl, COSM, -sl * SINM));
        float pr = expf(logit_r - 64.0f);

        sum = sum - pw + pr;
        float lse = 64.0f + logf(sum);
        loss = lse - logit_r;               // -logp[label]
    }
    sh[r] = loss;
    __syncthreads();
    #pragma unroll
    for (int s = MAXB / 2; s > 0; s >>= 1) {
        if (r < s) sh[r] += sh[r + s];
        __syncthreads();
    }
    if (r == 0) out[0] = sh[0] / (float)B;
}

// ----------------------------------------------------------------------------
extern "C" void kernel_launch(void* const* d_in, const int* in_sizes, int n_in,
                              void* d_out, int out_size) {
    const float* costh = (const float*)d_in[0];
    const float* eps   = (const float*)d_in[1];
    const int*   lab32 = (const int*)d_in[2];
    int B = in_sizes[2];            // 512
    int C = in_sizes[0] / B;        // 100000

    stats_kernel<<<1, MAXB>>>(costh, lab32, B, C);
    main_kernel<<<B * NSPLIT, 256>>>(costh, eps, C);
    finalize_kernel<<<1, MAXB>>>(costh, eps, lab32, (float*)d_out, B, C);
}